// round 15
// baseline (speedup 1.0000x reference)
#include <cuda_runtime.h>
#include <cuda_fp16.h>

#define NN 100000
#define NE 1600000
#define NF 128
#define NC 64
#define SCB 98   // scan blocks: ceil(100000/1024)

// ---------------- device scratch (allocation-free) ----------------
__device__ unsigned long long g_pk[NN];   // bits[44+): edge count, bits[0:44): sum(w)*2^32
__device__ float  g_dinv[NN];
__device__ int    g_rowptr[NN + 1];       // CSR by target node
__device__ int    g_rank[NE];             // edge's slot within its target's list
__device__ int    g_bsum[128];
__device__ int2   g_edge[NE];             // packed (src, raw weight bits)
__device__ uint2  g_h0[NN * 16];          // features as half2 pairs (128B/row)
__device__ uint2  g_h1[NN * 16];          // after hop 1

// half<->float helpers
static __device__ __forceinline__ float2 u2f(unsigned v) {
    __half2 h = *reinterpret_cast<__half2*>(&v);
    return __half22float2(h);
}
static __device__ __forceinline__ unsigned f2u(float a, float b) {
    __half2 h = __floats2half2_rn(a, b);
    return *reinterpret_cast<unsigned*>(&h);
}

// ---------------- init: pk = 0 (self-loop folded into decode) ----------------
__global__ void k_init() {
    int i = blockIdx.x * blockDim.x + threadIdx.x;
    if (i < NN) g_pk[i] = 0ULL;
}

// ---------------- edge pass: ONE u64 atomic = count + weighted degree + rank ----
__global__ void k_edge1(const int* __restrict__ ei, const float* __restrict__ ew) {
    int e = blockIdx.x * blockDim.x + threadIdx.x;
    if (e >= NE) return;
    int c = ei[NE + e];                       // target node
    unsigned long long v = (1ULL << 44)
        + (unsigned long long)(ew[e] * 4294967296.0f);
    unsigned long long old = atomicAdd(&g_pk[c], v);
    g_rank[e] = (int)(old >> 44);             // unique slot within target's list
}

// ---------------- scan1: per-block exclusive scan of counts ---------------------
__global__ void k_scan1() {
    __shared__ int sh[256];
    int t = threadIdx.x;
    int base = blockIdx.x * 1024 + t * 4;
    int v0 = 0, v1 = 0, v2 = 0, v3 = 0;
    if (base + 0 < NN) v0 = (int)(g_pk[base + 0] >> 44);
    if (base + 1 < NN) v1 = (int)(g_pk[base + 1] >> 44);
    if (base + 2 < NN) v2 = (int)(g_pk[base + 2] >> 44);
    if (base + 3 < NN) v3 = (int)(g_pk[base + 3] >> 44);
    int s = v0 + v1 + v2 + v3;
    sh[t] = s;
    __syncthreads();
    for (int off = 1; off < 256; off <<= 1) {
        int add = (t >= off) ? sh[t - off] : 0;
        __syncthreads();
        sh[t] += add;
        __syncthreads();
    }
    int ex = sh[t] - s;
    if (base + 0 < NN) g_rowptr[base + 0] = ex;
    if (base + 1 < NN) g_rowptr[base + 1] = ex + v0;
    if (base + 2 < NN) g_rowptr[base + 2] = ex + v0 + v1;
    if (base + 3 < NN) g_rowptr[base + 3] = ex + v0 + v1 + v2;
    if (t == 255) g_bsum[blockIdx.x] = sh[255];
}

// ---------------- scan3: block offset (scan2 fused) + rowptr + dinv -------------
__global__ void k_scan3() {
    __shared__ int sb[128];
    int t = threadIdx.x, b = blockIdx.x;
    // each block redundantly scans the 98 block sums (cheap, L2-resident)
    int v = (t < 128) ? ((t < SCB) ? g_bsum[t] : 0) : 0;
    if (t < 128) sb[t] = v;
    __syncthreads();
    for (int off = 1; off < 128; off <<= 1) {
        int add = (t < 128 && t >= off) ? sb[t - off] : 0;
        __syncthreads();
        if (t < 128) sb[t] += add;
        __syncthreads();
    }
    int off = sb[b] - g_bsum[b];   // exclusive prefix for this block
    int base = b * 1024 + t * 4;
#pragma unroll
    for (int i = 0; i < 4; i++) {
        int idx = base + i;
        if (idx < NN) {
            g_rowptr[idx] += off;
            // deg = 1.0 (self loop) + fixed-point edge-weight sum
            float deg = 1.0f +
                (float)(g_pk[idx] & ((1ULL << 44) - 1)) * 2.3283064365386963e-10f;
            g_dinv[idx] = rsqrtf(deg);
        }
    }
    if (b == SCB - 1 && t == 0) g_rowptr[NN] = NE;
}

// ---------------- scatter: atomic-free, dinv-free (raw weights) -----------------
__global__ void k_scatter(const int* __restrict__ ei, const float* __restrict__ ew) {
    int e = blockIdx.x * blockDim.x + threadIdx.x;
    if (e >= NE) return;
    int r = ei[e];
    int c = ei[NE + e];
    int pos = g_rowptr[c] + g_rank[e];
    g_edge[pos] = make_int2(r, __float_as_int(ew[e]));
}

// ---------------- GEMM: h0 = x @ W^T -> half2, fp16 tensor cores ----------------
#define HS 136   // smem row stride in halfs (128 + 8 pad -> conflict-free frags)
__global__ void k_gemmT(const float* __restrict__ x, const float* __restrict__ W) {
    __shared__ __half xs[64 * HS];
    __shared__ __half wsh[64 * HS];
    int tid = threadIdx.x;
    int warp = tid >> 5, lane = tid & 31;
    int g = lane >> 2, tg = lane & 3;
    int n0 = blockIdx.x * 64;

    for (int i = tid; i < 64 * 32; i += 128) {
        int r = i >> 5, q = i & 31;
        int xr = n0 + r; if (xr >= NN) xr = NN - 1;
        float4 v = ((const float4*)(x + (size_t)xr * NF))[q];
        __half2* dst = (__half2*)&xs[r * HS + q * 4];
        dst[0] = __floats2half2_rn(v.x, v.y);
        dst[1] = __floats2half2_rn(v.z, v.w);
    }
    for (int i = tid; i < 64 * 32; i += 128) {
        int r = i >> 5, q = i & 31;
        float4 v = ((const float4*)(W + (size_t)r * NF))[q];
        __half2* dst = (__half2*)&wsh[r * HS + q * 4];
        dst[0] = __floats2half2_rn(v.x, v.y);
        dst[1] = __floats2half2_rn(v.z, v.w);
    }
    __syncthreads();

    int row0 = warp * 16;
    float c[8][4];
#pragma unroll
    for (int j = 0; j < 8; j++)
#pragma unroll
        for (int q = 0; q < 4; q++) c[j][q] = 0.0f;

#pragma unroll
    for (int ks = 0; ks < 128; ks += 16) {
        unsigned a0 = *(const unsigned*)&xs[(row0 + g) * HS + ks + tg * 2];
        unsigned a1 = *(const unsigned*)&xs[(row0 + g + 8) * HS + ks + tg * 2];
        unsigned a2 = *(const unsigned*)&xs[(row0 + g) * HS + ks + 8 + tg * 2];
        unsigned a3 = *(const unsigned*)&xs[(row0 + g + 8) * HS + ks + 8 + tg * 2];
#pragma unroll
        for (int j = 0; j < 8; j++) {
            unsigned b0 = *(const unsigned*)&wsh[(j * 8 + g) * HS + ks + tg * 2];
            unsigned b1 = *(const unsigned*)&wsh[(j * 8 + g) * HS + ks + 8 + tg * 2];
            asm volatile(
                "mma.sync.aligned.m16n8k16.row.col.f32.f16.f16.f32 "
                "{%0,%1,%2,%3}, {%4,%5,%6,%7}, {%8,%9}, {%0,%1,%2,%3};"
                : "+f"(c[j][0]), "+f"(c[j][1]), "+f"(c[j][2]), "+f"(c[j][3])
                : "r"(a0), "r"(a1), "r"(a2), "r"(a3), "r"(b0), "r"(b1));
        }
    }

    unsigned* h0 = (unsigned*)g_h0;
    int nA = n0 + row0 + g;
    int nB = nA + 8;
#pragma unroll
    for (int j = 0; j < 8; j++) {
        if (nA < NN) h0[nA * 32 + j * 4 + tg] = f2u(c[j][0], c[j][1]);
        if (nB < NN) h0[nB * 32 + j * 4 + tg] = f2u(c[j][2], c[j][3]);
    }
}

// ---------------- prescale: h0 <- dinv * h0 (runs parallel with scatter) --------
__global__ void k_prescale() {
    int i = blockIdx.x * blockDim.x + threadIdx.x;
    if (i >= NN * 16) return;
    float dv = g_dinv[i >> 4];
    uint2 p = g_h0[i];
    float2 f0 = u2f(p.x), f1 = u2f(p.y);
    g_h0[i] = make_uint2(f2u(dv * f0.x, dv * f0.y), f2u(dv * f1.x, dv * f1.y));
}

// ---------------- SpMM hops (raw weights; dinv via feature scaling) -------------
__global__ void k_hop1() {
    int gid = blockIdx.x * blockDim.x + threadIdx.x;
    int node = gid >> 4;
    if (node >= NN) return;
    int lane = gid & 15;

    int s = g_rowptr[node];
    int e = g_rowptr[node + 1];
    float dv = g_dinv[node];
    uint2 p = g_h0[node * 16 + lane];
    float2 f0 = u2f(p.x), f1 = u2f(p.y);
    float a0 = f0.x, a1 = f0.y, a2 = f1.x, a3 = f1.y;   // self loop, w = 1

#pragma unroll 2
    for (int i = s; i < e; i++) {
        int2 m = g_edge[i];
        float w = __int_as_float(m.y);
        uint2 q = g_h0[m.x * 16 + lane];
        float2 g0 = u2f(q.x), g1 = u2f(q.y);
        a0 = fmaf(w, g0.x, a0);
        a1 = fmaf(w, g0.y, a1);
        a2 = fmaf(w, g1.x, a2);
        a3 = fmaf(w, g1.y, a3);
    }
    float s2 = dv * dv;   // D^-1/2 (this hop's out) * D^-1/2 (next hop's in)
    g_h1[node * 16 + lane] = make_uint2(f2u(s2 * a0, s2 * a1), f2u(s2 * a2, s2 * a3));
}

__global__ void k_hop2(float4* __restrict__ out, const float4* __restrict__ bias) {
    int gid = blockIdx.x * blockDim.x + threadIdx.x;
    int node = gid >> 4;
    if (node >= NN) return;
    int lane = gid & 15;

    int s = g_rowptr[node];
    int e = g_rowptr[node + 1];
    float dv = g_dinv[node];
    uint2 p = g_h1[node * 16 + lane];
    float2 f0 = u2f(p.x), f1 = u2f(p.y);
    float a0 = f0.x, a1 = f0.y, a2 = f1.x, a3 = f1.y;   // self loop, w = 1

#pragma unroll 2
    for (int i = s; i < e; i++) {
        int2 m = g_edge[i];
        float w = __int_as_float(m.y);
        uint2 q = g_h1[m.x * 16 + lane];
        float2 g0 = u2f(q.x), g1 = u2f(q.y);
        a0 = fmaf(w, g0.x, a0);
        a1 = fmaf(w, g0.y, a1);
        a2 = fmaf(w, g1.x, a2);
        a3 = fmaf(w, g1.y, a3);
    }
    float4 b = bias[lane];
    out[node * 16 + lane] = make_float4(fmaf(dv, a0, b.x), fmaf(dv, a1, b.y),
                                        fmaf(dv, a2, b.z), fmaf(dv, a3, b.w));
}

// ---------------- launch -------------------------------------------------------
extern "C" void kernel_launch(void* const* d_in, const int* in_sizes, int n_in,
                              void* d_out, int out_size) {
    const float* x    = (const float*)d_in[0];
    const int*   ei   = (const int*)d_in[1];     // int32 edge_index [2, NE]
    const float* ew   = (const float*)d_in[2];
    const float* Wl   = (const float*)d_in[3];
    const float* bias = (const float*)d_in[4];
    float4* out = (float4*)d_out;

    const int NB_N  = (NN + 255) / 256;        // 391
    const int NB_E  = (NE + 255) / 256;        // 6250
    const int NB_H  = (NN * 16 + 255) / 256;   // 6250
    const int NB_G  = (NN + 63) / 64;          // 1563

    cudaStream_t s2;
    cudaEvent_t evFork, evScan, evJoin;
    cudaStreamCreateWithFlags(&s2, cudaStreamNonBlocking);
    cudaEventCreateWithFlags(&evFork, cudaEventDisableTiming);
    cudaEventCreateWithFlags(&evScan, cudaEventDisableTiming);
    cudaEventCreateWithFlags(&evJoin, cudaEventDisableTiming);

    // fork: GEMM independent of CSR build
    cudaEventRecord(evFork, 0);
    cudaStreamWaitEvent(s2, evFork, 0);
    k_gemmT<<<NB_G, 128, 0, s2>>>(x, Wl);

    // CSR build on default stream
    k_init<<<NB_N, 256>>>();
    k_edge1<<<NB_E, 256>>>(ei, ew);
    k_scan1<<<SCB, 256>>>();
    k_scan3<<<SCB, 256>>>();
    cudaEventRecord(evScan, 0);                 // dinv + rowptr ready
    k_scatter<<<NB_E, 256>>>(ei, ew);           // parallel with prescale

    // side stream: prescale features (needs gemmT output + dinv)
    cudaStreamWaitEvent(s2, evScan, 0);
    k_prescale<<<NB_H, 256, 0, s2>>>();
    cudaEventRecord(evJoin, s2);

    // join, then hops
    cudaStreamWaitEvent(0, evJoin, 0);
    k_hop1<<<NB_H, 256>>>();
    k_hop2<<<NB_H, 256>>>(out, (const float4*)bias);

    cudaStreamCaptureStatus st = cudaStreamCaptureStatusNone;
    cudaStreamIsCapturing(0, &st);
    if (st == cudaStreamCaptureStatusNone) {
        cudaEventDestroy(evFork);
        cudaEventDestroy(evScan);
        cudaEventDestroy(evJoin);
        cudaStreamDestroy(s2);
    }
}

// round 16
// speedup vs baseline: 1.0904x; 1.0904x over previous
#include <cuda_runtime.h>
#include <cuda_fp16.h>

#define NN 100000
#define NE 1600000
#define NF 128
#define NC 64
#define SCB 98   // scan blocks: ceil(100000/1024)

// ---------------- device scratch (allocation-free) ----------------
__device__ unsigned long long g_pk[NN];   // bits[44+): edge count, bits[0:44): sum(w)*2^32
__device__ float  g_dinv[NN];
__device__ int    g_cnt[NN];              // scatter cursor
__device__ int    g_rowptr[NN + 1];       // CSR by target node
__device__ int    g_bsum[128];
__device__ int2   g_edge[NE];             // packed (src, normalized weight bits)
__device__ uint2  g_h0[NN * 16];          // x @ W^T as half2 pairs (128B/row)
__device__ uint2  g_h1[NN * 16];          // after hop 1

// half<->float helpers
static __device__ __forceinline__ float2 u2f(unsigned v) {
    __half2 h = *reinterpret_cast<__half2*>(&v);
    return __half22float2(h);
}
static __device__ __forceinline__ unsigned f2u(float a, float b) {
    __half2 h = __floats2half2_rn(a, b);
    return *reinterpret_cast<unsigned*>(&h);
}

// ---------------- init: pk = self-loop weight 1.0 (count 0) ----------------
__global__ void k_init() {
    int i = blockIdx.x * blockDim.x + threadIdx.x;
    if (i < NN) g_pk[i] = (1ULL << 32);       // w=1.0 in 32.32 fixed point
}

// ---------------- edge pass: ONE u64 atomic = count + weighted degree ----------
__global__ void k_edge1(const int* __restrict__ ei, const float* __restrict__ ew) {
    int e = blockIdx.x * blockDim.x + threadIdx.x;
    if (e >= NE) return;
    int c = ei[NE + e];                       // target node
    unsigned long long v = (1ULL << 44)
        + (unsigned long long)(ew[e] * 4294967296.0f);
    atomicAdd(&g_pk[c], v);
}

// ---------------- scan1: per-block exclusive scan of counts ---------------------
__global__ void k_scan1() {
    __shared__ int sh[256];
    int t = threadIdx.x;
    int base = blockIdx.x * 1024 + t * 4;
    int v0 = 0, v1 = 0, v2 = 0, v3 = 0;
    if (base + 0 < NN) v0 = (int)(g_pk[base + 0] >> 44);
    if (base + 1 < NN) v1 = (int)(g_pk[base + 1] >> 44);
    if (base + 2 < NN) v2 = (int)(g_pk[base + 2] >> 44);
    if (base + 3 < NN) v3 = (int)(g_pk[base + 3] >> 44);
    int s = v0 + v1 + v2 + v3;
    sh[t] = s;
    __syncthreads();
    for (int off = 1; off < 256; off <<= 1) {
        int add = (t >= off) ? sh[t - off] : 0;
        __syncthreads();
        sh[t] += add;
        __syncthreads();
    }
    int ex = sh[t] - s;
    if (base + 0 < NN) g_rowptr[base + 0] = ex;
    if (base + 1 < NN) g_rowptr[base + 1] = ex + v0;
    if (base + 2 < NN) g_rowptr[base + 2] = ex + v0 + v1;
    if (base + 3 < NN) g_rowptr[base + 3] = ex + v0 + v1 + v2;
    if (t == 255) g_bsum[blockIdx.x] = sh[255];
}

// ---------------- scan3: redundant scan of block sums + rowptr + cursor + dinv --
__global__ void k_scan3() {
    __shared__ int sb[128];
    int t = threadIdx.x, b = blockIdx.x;
    if (t < 128) sb[t] = (t < SCB) ? g_bsum[t] : 0;
    __syncthreads();
    for (int off = 1; off < 128; off <<= 1) {
        int add = (t < 128 && t >= off) ? sb[t - off] : 0;
        __syncthreads();
        if (t < 128) sb[t] += add;
        __syncthreads();
    }
    int off = sb[b] - g_bsum[b];   // exclusive prefix for this block
    int base = b * 1024 + t * 4;
#pragma unroll
    for (int i = 0; i < 4; i++) {
        int idx = base + i;
        if (idx < NN) {
            int v = g_rowptr[idx] + off;
            g_rowptr[idx] = v;
            g_cnt[idx] = v;
            float deg = (float)(g_pk[idx] & ((1ULL << 44) - 1)) * 2.3283064365386963e-10f;
            g_dinv[idx] = rsqrtf(deg);     // deg >= 1 always (self loop)
        }
    }
    if (b == SCB - 1 && t == 0) g_rowptr[NN] = NE;
}

// ---------------- scatter edges into CSR with normalized weights (packed) -------
__global__ void k_scatter(const int* __restrict__ ei, const float* __restrict__ ew) {
    int e = blockIdx.x * blockDim.x + threadIdx.x;
    if (e >= NE) return;
    int r = ei[e];
    int c = ei[NE + e];
    int pos = atomicAdd(&g_cnt[c], 1);
    float wn = g_dinv[r] * ew[e] * g_dinv[c];
    g_edge[pos] = make_int2(r, __float_as_int(wn));
}

// ---------------- GEMM: h0 = x @ W^T -> half2, fp16 tensor cores ----------------
#define HS 136   // smem row stride in halfs (128 + 8 pad -> conflict-free frags)
__global__ void k_gemmT(const float* __restrict__ x, const float* __restrict__ W) {
    __shared__ __half xs[64 * HS];
    __shared__ __half wsh[64 * HS];
    int tid = threadIdx.x;
    int warp = tid >> 5, lane = tid & 31;
    int g = lane >> 2, tg = lane & 3;
    int n0 = blockIdx.x * 64;

    for (int i = tid; i < 64 * 32; i += 128) {
        int r = i >> 5, q = i & 31;
        int xr = n0 + r; if (xr >= NN) xr = NN - 1;
        float4 v = ((const float4*)(x + (size_t)xr * NF))[q];
        __half2* dst = (__half2*)&xs[r * HS + q * 4];
        dst[0] = __floats2half2_rn(v.x, v.y);
        dst[1] = __floats2half2_rn(v.z, v.w);
    }
    for (int i = tid; i < 64 * 32; i += 128) {
        int r = i >> 5, q = i & 31;
        float4 v = ((const float4*)(W + (size_t)r * NF))[q];
        __half2* dst = (__half2*)&wsh[r * HS + q * 4];
        dst[0] = __floats2half2_rn(v.x, v.y);
        dst[1] = __floats2half2_rn(v.z, v.w);
    }
    __syncthreads();

    int row0 = warp * 16;
    float c[8][4];
#pragma unroll
    for (int j = 0; j < 8; j++)
#pragma unroll
        for (int q = 0; q < 4; q++) c[j][q] = 0.0f;

#pragma unroll
    for (int ks = 0; ks < 128; ks += 16) {
        unsigned a0 = *(const unsigned*)&xs[(row0 + g) * HS + ks + tg * 2];
        unsigned a1 = *(const unsigned*)&xs[(row0 + g + 8) * HS + ks + tg * 2];
        unsigned a2 = *(const unsigned*)&xs[(row0 + g) * HS + ks + 8 + tg * 2];
        unsigned a3 = *(const unsigned*)&xs[(row0 + g + 8) * HS + ks + 8 + tg * 2];
#pragma unroll
        for (int j = 0; j < 8; j++) {
            unsigned b0 = *(const unsigned*)&wsh[(j * 8 + g) * HS + ks + tg * 2];
            unsigned b1 = *(const unsigned*)&wsh[(j * 8 + g) * HS + ks + 8 + tg * 2];
            asm volatile(
                "mma.sync.aligned.m16n8k16.row.col.f32.f16.f16.f32 "
                "{%0,%1,%2,%3}, {%4,%5,%6,%7}, {%8,%9}, {%0,%1,%2,%3};"
                : "+f"(c[j][0]), "+f"(c[j][1]), "+f"(c[j][2]), "+f"(c[j][3])
                : "r"(a0), "r"(a1), "r"(a2), "r"(a3), "r"(b0), "r"(b1));
        }
    }

    unsigned* h0 = (unsigned*)g_h0;
    int nA = n0 + row0 + g;
    int nB = nA + 8;
#pragma unroll
    for (int j = 0; j < 8; j++) {
        if (nA < NN) h0[nA * 32 + j * 4 + tg] = f2u(c[j][0], c[j][1]);
        if (nB < NN) h0[nB * 32 + j * 4 + tg] = f2u(c[j][2], c[j][3]);
    }
}

// ---------------- SpMM hops (half rows, fp32 accumulate) ------------------------
__global__ void k_hop1() {
    int gid = blockIdx.x * blockDim.x + threadIdx.x;
    int node = gid >> 4;
    if (node >= NN) return;
    int lane = gid & 15;

    int s = g_rowptr[node];
    int e = g_rowptr[node + 1];
    float dv = g_dinv[node];
    float sw = dv * dv;
    uint2 p = g_h0[node * 16 + lane];
    float2 f0 = u2f(p.x), f1 = u2f(p.y);
    float a0 = sw * f0.x, a1 = sw * f0.y, a2 = sw * f1.x, a3 = sw * f1.y;

#pragma unroll 4
    for (int i = s; i < e; i++) {
        int2 m = g_edge[i];
        float w = __int_as_float(m.y);
        uint2 q = g_h0[m.x * 16 + lane];
        float2 g0 = u2f(q.x), g1 = u2f(q.y);
        a0 = fmaf(w, g0.x, a0);
        a1 = fmaf(w, g0.y, a1);
        a2 = fmaf(w, g1.x, a2);
        a3 = fmaf(w, g1.y, a3);
    }
    g_h1[node * 16 + lane] = make_uint2(f2u(a0, a1), f2u(a2, a3));
}

__global__ void k_hop2(float4* __restrict__ out, const float4* __restrict__ bias) {
    int gid = blockIdx.x * blockDim.x + threadIdx.x;
    int node = gid >> 4;
    if (node >= NN) return;
    int lane = gid & 15;

    int s = g_rowptr[node];
    int e = g_rowptr[node + 1];
    float dv = g_dinv[node];
    float sw = dv * dv;
    uint2 p = g_h1[node * 16 + lane];
    float2 f0 = u2f(p.x), f1 = u2f(p.y);
    float a0 = sw * f0.x, a1 = sw * f0.y, a2 = sw * f1.x, a3 = sw * f1.y;

#pragma unroll 4
    for (int i = s; i < e; i++) {
        int2 m = g_edge[i];
        float w = __int_as_float(m.y);
        uint2 q = g_h1[m.x * 16 + lane];
        float2 g0 = u2f(q.x), g1 = u2f(q.y);
        a0 = fmaf(w, g0.x, a0);
        a1 = fmaf(w, g0.y, a1);
        a2 = fmaf(w, g1.x, a2);
        a3 = fmaf(w, g1.y, a3);
    }
    float4 b = bias[lane];
    out[node * 16 + lane] = make_float4(a0 + b.x, a1 + b.y, a2 + b.z, a3 + b.w);
}

// ---------------- launch: CSR build (default stream) || GEMM (side stream) ------
extern "C" void kernel_launch(void* const* d_in, const int* in_sizes, int n_in,
                              void* d_out, int out_size) {
    const float* x    = (const float*)d_in[0];
    const int*   ei   = (const int*)d_in[1];     // int32 edge_index [2, NE]
    const float* ew   = (const float*)d_in[2];
    const float* Wl   = (const float*)d_in[3];
    const float* bias = (const float*)d_in[4];
    float4* out = (float4*)d_out;

    const int NB_N  = (NN + 255) / 256;        // 391
    const int NB_E  = (NE + 255) / 256;        // 6250
    const int NB_H  = (NN * 16 + 255) / 256;   // 6250
    const int NB_G  = (NN + 63) / 64;          // 1563

    cudaStream_t s2;
    cudaEvent_t evFork, evJoin;
    cudaStreamCreateWithFlags(&s2, cudaStreamNonBlocking);
    cudaEventCreateWithFlags(&evFork, cudaEventDisableTiming);
    cudaEventCreateWithFlags(&evJoin, cudaEventDisableTiming);

    // fork: GEMM independent of CSR build
    cudaEventRecord(evFork, 0);
    cudaStreamWaitEvent(s2, evFork, 0);
    k_gemmT<<<NB_G, 128, 0, s2>>>(x, Wl);
    cudaEventRecord(evJoin, s2);

    // CSR build on default stream
    k_init<<<NB_N, 256>>>();
    k_edge1<<<NB_E, 256>>>(ei, ew);
    k_scan1<<<SCB, 256>>>();
    k_scan3<<<SCB, 256>>>();
    k_scatter<<<NB_E, 256>>>(ei, ew);

    // join, then hops
    cudaStreamWaitEvent(0, evJoin, 0);
    k_hop1<<<NB_H, 256>>>();
    k_hop2<<<NB_H, 256>>>(out, (const float4*)bias);

    cudaStreamCaptureStatus st = cudaStreamCaptureStatusNone;
    cudaStreamIsCapturing(0, &st);
    if (st == cudaStreamCaptureStatusNone) {
        cudaEventDestroy(evFork);
        cudaEventDestroy(evJoin);
        cudaStreamDestroy(s2);
    }
}

// round 17
// speedup vs baseline: 1.0981x; 1.0071x over previous
#include <cuda_runtime.h>
#include <cuda_fp16.h>

#define NN 100000
#define NE 1600000
#define NF 128
#define NC 64
#define SCB 98   // scan blocks: ceil(100000/1024)

// ---------------- device scratch (allocation-free) ----------------
__device__ unsigned long long g_pk[NN];   // bits[44+): edge count, bits[0:44): sum(w)*2^32
__device__ float  g_dinv[NN];
__device__ int    g_cnt[NN];              // scatter cursor
__device__ int    g_rowptr[NN + 1];       // CSR by target node
__device__ int    g_bsum[128];
__device__ int    g_done;                 // flat scan barrier counter
__device__ int2   g_edge[NE];             // packed (src, dinv[src]*w bits)
__device__ uint2  g_h0[NN * 16];          // x @ W^T as half2 pairs (128B/row)
__device__ uint2  g_h1[NN * 16];          // after hop 1

// half<->float helpers
static __device__ __forceinline__ float2 u2f(unsigned v) {
    __half2 h = *reinterpret_cast<__half2*>(&v);
    return __half22float2(h);
}
static __device__ __forceinline__ unsigned f2u(float a, float b) {
    __half2 h = __floats2half2_rn(a, b);
    return *reinterpret_cast<unsigned*>(&h);
}

// ---------------- init: pk = self-loop weight 1.0 (count 0) ----------------
__global__ void k_init() {
    int i = blockIdx.x * blockDim.x + threadIdx.x;
    if (i < NN) g_pk[i] = (1ULL << 32);       // w=1.0 in 32.32 fixed point
    if (i == 0) g_done = 0;
}

// ---------------- edge pass: u64 atomic = count + weighted degree, 2 edges/thr --
__global__ void k_edge1(const int* __restrict__ ei, const float* __restrict__ ew) {
    int e2 = (blockIdx.x * blockDim.x + threadIdx.x) * 2;
    if (e2 >= NE) return;
    int2   c = *(const int2*)(ei + NE + e2);
    float2 w = *(const float2*)(ew + e2);
    unsigned long long v0 = (1ULL << 44) + (unsigned long long)(w.x * 4294967296.0f);
    unsigned long long v1 = (1ULL << 44) + (unsigned long long)(w.y * 4294967296.0f);
    atomicAdd(&g_pk[c.x], v0);
    atomicAdd(&g_pk[c.y], v1);
}

// ---------------- single-kernel scan (flat barrier, all 98 blocks resident) -----
__global__ void k_scan() {
    __shared__ int sh[256];
    __shared__ int sb[128];
    int t = threadIdx.x, b = blockIdx.x;
    int base = b * 1024 + t * 4;

    unsigned long long pk[4];
    int v[4], s = 0;
#pragma unroll
    for (int i = 0; i < 4; i++) {
        int idx = base + i;
        pk[i] = (idx < NN) ? g_pk[idx] : 0ULL;
        v[i] = (int)(pk[i] >> 44);
        s += v[i];
    }
    sh[t] = s;
    __syncthreads();
    for (int off = 1; off < 256; off <<= 1) {
        int add = (t >= off) ? sh[t - off] : 0;
        __syncthreads();
        sh[t] += add;
        __syncthreads();
    }
    int ex = sh[t] - s;                 // exclusive prefix within block
    int btot = sh[255];

    // publish block sum, flat barrier (single L2 round trip, no chaining)
    if (t == 0) {
        g_bsum[b] = btot;
        __threadfence();
        atomicAdd(&g_done, 1);
        while (*(volatile int*)&g_done < SCB) {}
    }
    __syncthreads();
    __threadfence();

    if (t < 128) sb[t] = (t < SCB) ? g_bsum[t] : 0;
    __syncthreads();
    for (int off = 1; off < 128; off <<= 1) {
        int add = (t < 128 && t >= off) ? sb[t - off] : 0;
        __syncthreads();
        if (t < 128) sb[t] += add;
        __syncthreads();
    }
    int off = sb[b] - btot + ex;        // global exclusive prefix for this thread
#pragma unroll
    for (int i = 0; i < 4; i++) {
        int idx = base + i;
        if (idx < NN) {
            g_rowptr[idx] = off;
            g_cnt[idx] = off;
            off += v[i];
            float deg = (float)(pk[i] & ((1ULL << 44) - 1)) * 2.3283064365386963e-10f;
            g_dinv[idx] = rsqrtf(deg);  // deg >= 1 always (self loop)
        }
    }
    if (b == SCB - 1 && t == 0) g_rowptr[NN] = NE;
}

// ---------------- scatter: w~ = dinv[src]*w (no target dinv), 2 edges/thread ----
__global__ void k_scatter(const int* __restrict__ ei, const float* __restrict__ ew) {
    int e2 = (blockIdx.x * blockDim.x + threadIdx.x) * 2;
    if (e2 >= NE) return;
    int2   r = *(const int2*)(ei + e2);
    int2   c = *(const int2*)(ei + NE + e2);
    float2 w = *(const float2*)(ew + e2);
    int p0 = atomicAdd(&g_cnt[c.x], 1);
    int p1 = atomicAdd(&g_cnt[c.y], 1);
    g_edge[p0] = make_int2(r.x, __float_as_int(g_dinv[r.x] * w.x));
    g_edge[p1] = make_int2(r.y, __float_as_int(g_dinv[r.y] * w.y));
}

// ---------------- GEMM: h0 = x @ W^T -> half2, fp16 tensor cores ----------------
#define HS 136   // smem row stride in halfs (128 + 8 pad -> conflict-free frags)
__global__ void k_gemmT(const float* __restrict__ x, const float* __restrict__ W) {
    __shared__ __half xs[64 * HS];
    __shared__ __half wsh[64 * HS];
    int tid = threadIdx.x;
    int warp = tid >> 5, lane = tid & 31;
    int g = lane >> 2, tg = lane & 3;
    int n0 = blockIdx.x * 64;

    for (int i = tid; i < 64 * 32; i += 128) {
        int r = i >> 5, q = i & 31;
        int xr = n0 + r; if (xr >= NN) xr = NN - 1;
        float4 v = ((const float4*)(x + (size_t)xr * NF))[q];
        __half2* dst = (__half2*)&xs[r * HS + q * 4];
        dst[0] = __floats2half2_rn(v.x, v.y);
        dst[1] = __floats2half2_rn(v.z, v.w);
    }
    for (int i = tid; i < 64 * 32; i += 128) {
        int r = i >> 5, q = i & 31;
        float4 v = ((const float4*)(W + (size_t)r * NF))[q];
        __half2* dst = (__half2*)&wsh[r * HS + q * 4];
        dst[0] = __floats2half2_rn(v.x, v.y);
        dst[1] = __floats2half2_rn(v.z, v.w);
    }
    __syncthreads();

    int row0 = warp * 16;
    float c[8][4];
#pragma unroll
    for (int j = 0; j < 8; j++)
#pragma unroll
        for (int q = 0; q < 4; q++) c[j][q] = 0.0f;

#pragma unroll
    for (int ks = 0; ks < 128; ks += 16) {
        unsigned a0 = *(const unsigned*)&xs[(row0 + g) * HS + ks + tg * 2];
        unsigned a1 = *(const unsigned*)&xs[(row0 + g + 8) * HS + ks + tg * 2];
        unsigned a2 = *(const unsigned*)&xs[(row0 + g) * HS + ks + 8 + tg * 2];
        unsigned a3 = *(const unsigned*)&xs[(row0 + g + 8) * HS + ks + 8 + tg * 2];
#pragma unroll
        for (int j = 0; j < 8; j++) {
            unsigned b0 = *(const unsigned*)&wsh[(j * 8 + g) * HS + ks + tg * 2];
            unsigned b1 = *(const unsigned*)&wsh[(j * 8 + g) * HS + ks + 8 + tg * 2];
            asm volatile(
                "mma.sync.aligned.m16n8k16.row.col.f32.f16.f16.f32 "
                "{%0,%1,%2,%3}, {%4,%5,%6,%7}, {%8,%9}, {%0,%1,%2,%3};"
                : "+f"(c[j][0]), "+f"(c[j][1]), "+f"(c[j][2]), "+f"(c[j][3])
                : "r"(a0), "r"(a1), "r"(a2), "r"(a3), "r"(b0), "r"(b1));
        }
    }

    unsigned* h0 = (unsigned*)g_h0;
    int nA = n0 + row0 + g;
    int nB = nA + 8;
#pragma unroll
    for (int j = 0; j < 8; j++) {
        if (nA < NN) h0[nA * 32 + j * 4 + tg] = f2u(c[j][0], c[j][1]);
        if (nB < NN) h0[nB * 32 + j * 4 + tg] = f2u(c[j][2], c[j][3]);
    }
}

// ---------------- SpMM hops: out_c = dv_c*(dv_c*x_c + sum w~ * x_u) -------------
__global__ void k_hop1() {
    int gid = blockIdx.x * blockDim.x + threadIdx.x;
    int node = gid >> 4;
    if (node >= NN) return;
    int lane = gid & 15;

    int s = g_rowptr[node];
    int e = g_rowptr[node + 1];
    float dv = g_dinv[node];
    uint2 p = g_h0[node * 16 + lane];
    float2 f0 = u2f(p.x), f1 = u2f(p.y);
    float a0 = dv * f0.x, a1 = dv * f0.y, a2 = dv * f1.x, a3 = dv * f1.y;

#pragma unroll 4
    for (int i = s; i < e; i++) {
        int2 m = g_edge[i];
        float w = __int_as_float(m.y);
        uint2 q = g_h0[m.x * 16 + lane];
        float2 g0 = u2f(q.x), g1 = u2f(q.y);
        a0 = fmaf(w, g0.x, a0);
        a1 = fmaf(w, g0.y, a1);
        a2 = fmaf(w, g1.x, a2);
        a3 = fmaf(w, g1.y, a3);
    }
    g_h1[node * 16 + lane] = make_uint2(f2u(dv * a0, dv * a1), f2u(dv * a2, dv * a3));
}

__global__ void k_hop2(float4* __restrict__ out, const float4* __restrict__ bias) {
    int gid = blockIdx.x * blockDim.x + threadIdx.x;
    int node = gid >> 4;
    if (node >= NN) return;
    int lane = gid & 15;

    int s = g_rowptr[node];
    int e = g_rowptr[node + 1];
    float dv = g_dinv[node];
    uint2 p = g_h1[node * 16 + lane];
    float2 f0 = u2f(p.x), f1 = u2f(p.y);
    float a0 = dv * f0.x, a1 = dv * f0.y, a2 = dv * f1.x, a3 = dv * f1.y;

#pragma unroll 4
    for (int i = s; i < e; i++) {
        int2 m = g_edge[i];
        float w = __int_as_float(m.y);
        uint2 q = g_h1[m.x * 16 + lane];
        float2 g0 = u2f(q.x), g1 = u2f(q.y);
        a0 = fmaf(w, g0.x, a0);
        a1 = fmaf(w, g0.y, a1);
        a2 = fmaf(w, g1.x, a2);
        a3 = fmaf(w, g1.y, a3);
    }
    float4 b = bias[lane];
    out[node * 16 + lane] = make_float4(fmaf(dv, a0, b.x), fmaf(dv, a1, b.y),
                                        fmaf(dv, a2, b.z), fmaf(dv, a3, b.w));
}

// ---------------- launch: CSR build (default stream) || GEMM (side stream) ------
extern "C" void kernel_launch(void* const* d_in, const int* in_sizes, int n_in,
                              void* d_out, int out_size) {
    const float* x    = (const float*)d_in[0];
    const int*   ei   = (const int*)d_in[1];     // int32 edge_index [2, NE]
    const float* ew   = (const float*)d_in[2];
    const float* Wl   = (const float*)d_in[3];
    const float* bias = (const float*)d_in[4];
    float4* out = (float4*)d_out;

    const int NB_N  = (NN + 255) / 256;        // 391
    const int NB_E2 = (NE / 2 + 255) / 256;    // 3125
    const int NB_H  = (NN * 16 + 255) / 256;   // 6250
    const int NB_G  = (NN + 63) / 64;          // 1563

    cudaStream_t s2;
    cudaEvent_t evFork, evJoin;
    cudaStreamCreateWithFlags(&s2, cudaStreamNonBlocking);
    cudaEventCreateWithFlags(&evFork, cudaEventDisableTiming);
    cudaEventCreateWithFlags(&evJoin, cudaEventDisableTiming);

    // fork: GEMM independent of CSR build
    cudaEventRecord(evFork, 0);
    cudaStreamWaitEvent(s2, evFork, 0);
    k_gemmT<<<NB_G, 128, 0, s2>>>(x, Wl);
    cudaEventRecord(evJoin, s2);

    // CSR build on default stream
    k_init<<<NB_N, 256>>>();
    k_edge1<<<NB_E2, 256>>>(ei, ew);
    k_scan<<<SCB, 256>>>();
    k_scatter<<<NB_E2, 256>>>(ei, ew);

    // join, then hops
    cudaStreamWaitEvent(0, evJoin, 0);
    k_hop1<<<NB_H, 256>>>();
    k_hop2<<<NB_H, 256>>>(out, (const float4*)bias);

    cudaStreamCaptureStatus st = cudaStreamCaptureStatusNone;
    cudaStreamIsCapturing(0, &st);
    if (st == cudaStreamCaptureStatusNone) {
        cudaEventDestroy(evFork);
        cudaEventDestroy(evJoin);
        cudaStreamDestroy(s2);
    }
}